// round 1
// baseline (speedup 1.0000x reference)
#include <cuda_runtime.h>

#define NB   64
#define CC   64
#define TT   300
#define VV   25
#define TV   7500      // TT*VV
#define ICn  16
#define OCn  64
#define KS   3
#define KT   9
#define YSZ  30720000  // NB*CC*TV
#define BN_CNT 480000.0f

// ------------------------- scratch (device globals) -------------------------
__device__ float g_fa[KS*NB*ICn*TV];        // 5.76M
__device__ float g_fb[KS*NB*ICn*TV];        // 5.76M
__device__ float g_S [KS*NB*VV*VV];         // 120K
__device__ float g_u [KS*NB*OCn*TV];        // 92.16M  (368MB)
__device__ float g_y1[(size_t)NB*OCn*TV];   // 30.72M  (123MB)
__device__ float g_ps[NB*OCn];
__device__ float g_pq[NB*OCn];
__device__ float g_stats[4*OCn];            // [sum1, sq1, sum2, sq2]

// ------------------------- K1: fa/fb 1x1 projections ------------------------
// fa[k,n,o,t,v] = sum_c Wa[k,o,c]*x[n,c,t,v] + ba[k,o]; same for fb.
// 96 output rows (48 fa + 48 fb). 16-row x 4-tv register blocking.
__global__ void k_projab(const float* __restrict__ x, const float* __restrict__ Wa,
                         const float* __restrict__ ba, const float* __restrict__ Wb,
                         const float* __restrict__ bb) {
    __shared__ float ws[96*64];
    int tid = threadIdx.x;
    for (int i = tid; i < 48*64; i += 256) { ws[i] = Wa[i]; ws[48*64 + i] = Wb[i]; }
    __syncthreads();
    int n = blockIdx.y;
    int base = blockIdx.x * 1024 + tid;
    const float* xn = x + n * CC * TV;

    for (int p = 0; p < 6; p++) {
        float acc[16][4];
        #pragma unroll
        for (int j = 0; j < 16; j++) {
            acc[j][0] = acc[j][1] = acc[j][2] = acc[j][3] = 0.f;
        }
        #pragma unroll 4
        for (int c = 0; c < 64; c++) {
            float xc[4];
            #pragma unroll
            for (int m = 0; m < 4; m++) {
                int tv = base + m * 256;
                xc[m] = (tv < TV) ? xn[c * TV + tv] : 0.f;
            }
            #pragma unroll
            for (int j = 0; j < 16; j++) {
                float w = ws[(p * 16 + j) * 64 + c];
                #pragma unroll
                for (int m = 0; m < 4; m++) acc[j][m] = fmaf(w, xc[m], acc[j][m]);
            }
        }
        #pragma unroll
        for (int j = 0; j < 16; j++) {
            int r = p * 16 + j;
            float bias;
            float* out;
            if (r < 48) {
                bias = ba[r];
                out = g_fa + ((r >> 4) * NB * ICn + n * ICn + (r & 15)) * TV;
            } else {
                int r2 = r - 48;
                bias = bb[r2];
                out = g_fb + ((r2 >> 4) * NB * ICn + n * ICn + (r2 & 15)) * TV;
            }
            #pragma unroll
            for (int m = 0; m < 4; m++) {
                int tv = base + m * 256;
                if (tv < TV) out[tv] = acc[j][m] + bias;
            }
        }
    }
}

// ------------------------- K1b: Wd 1x1 projection ---------------------------
// u[k,n,o,t,v] = sum_c Wd[k,o,c]*x[n,c,t,v]   (192 rows, two weight halves)
__global__ void k_projd(const float* __restrict__ x, const float* __restrict__ Wd) {
    __shared__ float ws[96*64];
    int tid = threadIdx.x;
    int n = blockIdx.y;
    int base = blockIdx.x * 1024 + tid;
    const float* xn = x + n * CC * TV;

    for (int h = 0; h < 2; h++) {
        __syncthreads();
        for (int i = tid; i < 96*64; i += 256) ws[i] = Wd[h * 96 * 64 + i];
        __syncthreads();
        for (int p = 0; p < 6; p++) {
            float acc[16][4];
            #pragma unroll
            for (int j = 0; j < 16; j++) {
                acc[j][0] = acc[j][1] = acc[j][2] = acc[j][3] = 0.f;
            }
            #pragma unroll 4
            for (int c = 0; c < 64; c++) {
                float xc[4];
                #pragma unroll
                for (int m = 0; m < 4; m++) {
                    int tv = base + m * 256;
                    xc[m] = (tv < TV) ? xn[c * TV + tv] : 0.f;
                }
                #pragma unroll
                for (int j = 0; j < 16; j++) {
                    float w = ws[(p * 16 + j) * 64 + c];
                    #pragma unroll
                    for (int m = 0; m < 4; m++) acc[j][m] = fmaf(w, xc[m], acc[j][m]);
                }
            }
            #pragma unroll
            for (int j = 0; j < 16; j++) {
                int r = h * 96 + p * 16 + j;           // r = k*64 + o
                float* out = g_u + ((r >> 6) * NB * OCn + n * OCn + (r & 63)) * TV;
                #pragma unroll
                for (int m = 0; m < 4; m++) {
                    int tv = base + m * 256;
                    if (tv < TV) out[tv] = acc[j][m];
                }
            }
        }
    }
}

// ------------------------- K2: attention scores + softmax + A ---------------
// S[k,n,v,w] = softmax_v( sum_{o,t} fa[..v]*fb[..w] / 4800 ) + (adj+PA)[k,v,w]
// fa block for (k,n) is exactly a [4800][25] row-major matrix.
__global__ void k_scoreS(const float* __restrict__ adj, const float* __restrict__ PA) {
    int kk = blockIdx.x / NB, n = blockIdx.x % NB;
    const float* fa = g_fa + (kk * NB * ICn + n * ICn) * TV;
    const float* fb = g_fb + (kk * NB * ICn + n * ICn) * TV;
    __shared__ float as[64*25], bs[64*25], Ssm[625];
    int tid = threadIdx.x;                 // 640 threads
    int v = tid / 25, w = tid - v * 25;
    bool act = tid < 625;
    float acc = 0.f;
    for (int d0 = 0; d0 < 4800; d0 += 64) {
        for (int i = tid; i < 1600; i += 640) {
            as[i] = fa[d0 * 25 + i];
            bs[i] = fb[d0 * 25 + i];
        }
        __syncthreads();
        if (act) {
            #pragma unroll 8
            for (int d = 0; d < 64; d++) acc = fmaf(as[d*25 + v], bs[d*25 + w], acc);
        }
        __syncthreads();
    }
    if (act) Ssm[tid] = acc * (1.f / 4800.f);
    __syncthreads();
    if (tid < 25) {                        // tid = w; softmax over v
        int wq = tid;
        float m = -1e30f;
        #pragma unroll
        for (int vi = 0; vi < 25; vi++) m = fmaxf(m, Ssm[vi*25 + wq]);
        float e[25]; float s = 0.f;
        #pragma unroll
        for (int vi = 0; vi < 25; vi++) { e[vi] = expf(Ssm[vi*25 + wq] - m); s += e[vi]; }
        float inv = 1.f / s;
        #pragma unroll
        for (int vi = 0; vi < 25; vi++) {
            int ai = (kk * VV + vi) * VV + wq;
            g_S[(kk * NB + n) * 625 + vi * 25 + wq] = e[vi] * inv + adj[ai] + PA[ai];
        }
    }
}

// ------------------------- K3: V-mix + subset sum + bd ----------------------
// y_pre[n,o,t,w] = sum_k sum_v u[k,n,o,t,v]*S[k,n,v,w] + sum_k bd[k,o]
__global__ void k_mix(const float* __restrict__ bd) {
    int n = blockIdx.y;
    __shared__ float Ss[3*625];
    for (int i = threadIdx.x; i < 1875; i += 256) {
        int k = i / 625, r = i - k * 625;
        Ss[i] = g_S[(k * NB + n) * 625 + r];
    }
    __syncthreads();
    int idx = blockIdx.x * 256 + threadIdx.x;   // exactly 64*300
    int o = idx / TT, t = idx - o * TT;
    float b = bd[o] + bd[64 + o] + bd[128 + o];
    float acc[25];
    #pragma unroll
    for (int w = 0; w < 25; w++) acc[w] = b;
    #pragma unroll
    for (int k = 0; k < 3; k++) {
        const float* up = g_u + (size_t)(k * NB * OCn + n * OCn + o) * TV + t * 25;
        const float* sp = Ss + k * 625;
        #pragma unroll 5
        for (int v = 0; v < 25; v++) {
            float uv = up[v];
            #pragma unroll
            for (int w = 0; w < 25; w++) acc[w] = fmaf(uv, sp[v*25 + w], acc[w]);
        }
    }
    float* yo = g_y1 + (size_t)(n * OCn + o) * TV + t * 25;
    #pragma unroll
    for (int w = 0; w < 25; w++) yo[w] = acc[w];
}

// ------------------------- BN stats (deterministic 2-stage) -----------------
__device__ __forceinline__ void bn_part_body(const float* p) {
    float s = 0.f, q = 0.f;
    for (int i = threadIdx.x; i < TV; i += 256) { float v = p[i]; s += v; q = fmaf(v, v, q); }
    __shared__ float sh[512];
    sh[threadIdx.x] = s; sh[256 + threadIdx.x] = q;
    __syncthreads();
    for (int st = 128; st; st >>= 1) {
        if (threadIdx.x < st) {
            sh[threadIdx.x] += sh[threadIdx.x + st];
            sh[256 + threadIdx.x] += sh[256 + threadIdx.x + st];
        }
        __syncthreads();
    }
    if (threadIdx.x == 0) {
        int n = blockIdx.x, o = blockIdx.y;
        g_ps[o * 64 + n] = sh[0];
        g_pq[o * 64 + n] = sh[256];
    }
}
__global__ void k_part_y1() { bn_part_body(g_y1 + (size_t)(blockIdx.x * 64 + blockIdx.y) * TV); }
__global__ void k_part_src(const float* __restrict__ s) { bn_part_body(s + (size_t)(blockIdx.x * 64 + blockIdx.y) * TV); }

__global__ void k_bnfinal(int off) {
    int o = threadIdx.x;
    if (o < 64) {
        float s = 0.f, q = 0.f;
        for (int n = 0; n < 64; n++) { s += g_ps[o * 64 + n]; q += g_pq[o * 64 + n]; }
        g_stats[off + o] = s;
        g_stats[off + 64 + o] = q;
    }
}

// ------------------------- BN apply + residual + relu -----------------------
__device__ __forceinline__ float bn_val(float src, const float* __restrict__ gamma,
                                        const float* __restrict__ beta, int soff, int c, float xid) {
    const float inv = 1.f / BN_CNT;
    float mu  = g_stats[soff + c] * inv;
    float var = fmaf(-mu, mu, g_stats[soff + 64 + c] * inv);
    float sc  = rsqrtf(var + 1e-5f) * gamma[c];
    float v   = (src - mu) * sc + beta[c] + xid;
    return fmaxf(v, 0.f);
}
__global__ void k_bn1(const float* __restrict__ x, const float* __restrict__ g1,
                      const float* __restrict__ b1) {
    int idx = blockIdx.x * 256 + threadIdx.x;
    if (idx >= YSZ) return;
    int c = (idx / TV) & 63;
    g_y1[idx] = bn_val(g_y1[idx], g1, b1, 0, c, x[idx]);
}
__global__ void k_bn2(float* __restrict__ out, const float* __restrict__ x,
                      const float* __restrict__ g2, const float* __restrict__ b2) {
    int idx = blockIdx.x * 256 + threadIdx.x;
    if (idx >= YSZ) return;
    int c = (idx / TV) & 63;
    out[idx] = bn_val(out[idx], g2, b2, 128, c, x[idx]);
}

// ------------------------- K6: temporal conv (implicit GEMM) ----------------
// conv[n,o,t,w] = sum_{c,kt} Wt[o,c,kt]*y1[n,c,t+kt-4,w] + bt[o]
// With tw = t*25+w, the kt shift is tw + 25*(kt-4); t-padding == tw bounds check.
// Block: fixed n, 256-tw tile, all 64 o. Thread: 8 o x 8 tw micro-tile.
__global__ void __launch_bounds__(256) k_tcn(const float* __restrict__ Wt,
                                             const float* __restrict__ bt,
                                             float* __restrict__ out) {
    __shared__ float ys[8 * 456];
    __shared__ float wsm[8 * 9 * 64];
    int n = blockIdx.y;
    int tile0 = blockIdx.x * 256;
    int tid = threadIdx.x;
    int ty = tid >> 5, tx = tid & 31;     // warp = fixed ty -> weight LDS broadcast
    int ob = ty * 8;
    float acc[64];
    #pragma unroll
    for (int i = 0; i < 64; i++) acc[i] = 0.f;

    for (int c0 = 0; c0 < 64; c0 += 8) {
        __syncthreads();
        for (int i = tid; i < 8 * 456; i += 256) {
            int c = i / 456, off = i - c * 456;
            int tw = tile0 - 100 + off;
            ys[i] = (tw >= 0 && tw < TV) ? g_y1[(size_t)(n * CC + c0 + c) * TV + tw] : 0.f;
        }
        for (int i = tid; i < 8 * 9 * 64; i += 256) {
            int o = i & 63, ck = i >> 6;
            int c = ck / 9, kt = ck - c * 9;
            wsm[i] = Wt[(o * 64 + c0 + c) * 9 + kt];
        }
        __syncthreads();
        for (int c = 0; c < 8; c++) {
            #pragma unroll 3
            for (int kt = 0; kt < 9; kt++) {
                float yv[8];
                int ybase = c * 456 + 100 + 25 * (kt - 4) + tx;
                #pragma unroll
                for (int j = 0; j < 8; j++) yv[j] = ys[ybase + 32 * j];
                #pragma unroll
                for (int oi = 0; oi < 8; oi++) {
                    float wv = wsm[(c * 9 + kt) * 64 + ob + oi];
                    #pragma unroll
                    for (int j = 0; j < 8; j++)
                        acc[oi * 8 + j] = fmaf(wv, yv[j], acc[oi * 8 + j]);
                }
            }
        }
    }
    #pragma unroll
    for (int oi = 0; oi < 8; oi++) {
        float bv = bt[ob + oi];
        #pragma unroll
        for (int j = 0; j < 8; j++) {
            int tw = tile0 + tx + 32 * j;
            if (tw < TV) out[(size_t)(n * OCn + ob + oi) * TV + tw] = acc[oi * 8 + j] + bv;
        }
    }
}

// ------------------------- K9: adj passthrough ------------------------------
__global__ void k_copyadj(const float* __restrict__ adj, float* __restrict__ out, int count) {
    int i = blockIdx.x * 256 + threadIdx.x;
    if (i < count) out[YSZ + i] = adj[i];
}

// ------------------------- launch -------------------------------------------
extern "C" void kernel_launch(void* const* d_in, const int* in_sizes, int n_in,
                              void* d_out, int out_size) {
    const float* x   = (const float*)d_in[0];
    const float* adj = (const float*)d_in[1];
    const float* PA  = (const float*)d_in[2];
    const float* Wa  = (const float*)d_in[3];
    const float* ba  = (const float*)d_in[4];
    const float* Wb  = (const float*)d_in[5];
    const float* bb  = (const float*)d_in[6];
    const float* Wd  = (const float*)d_in[7];
    const float* bd  = (const float*)d_in[8];
    const float* g1  = (const float*)d_in[9];
    const float* b1  = (const float*)d_in[10];
    const float* Wt  = (const float*)d_in[11];
    const float* bt  = (const float*)d_in[12];
    const float* g2  = (const float*)d_in[13];
    const float* b2  = (const float*)d_in[14];
    float* out = (float*)d_out;

    k_projab<<<dim3(8, 64), 256>>>(x, Wa, ba, Wb, bb);
    k_projd <<<dim3(8, 64), 256>>>(x, Wd);
    k_scoreS<<<192, 640>>>(adj, PA);
    k_mix   <<<dim3(75, 64), 256>>>(bd);

    k_part_y1<<<dim3(64, 64), 256>>>();
    k_bnfinal<<<1, 64>>>(0);
    k_bn1<<<(YSZ + 255) / 256, 256>>>(x, g1, b1);

    k_tcn<<<dim3(30, 64), 256>>>(Wt, bt, out);

    k_part_src<<<dim3(64, 64), 256>>>(out);
    k_bnfinal<<<1, 64>>>(128);
    k_bn2<<<(YSZ + 255) / 256, 256>>>(out, x, g2, b2);

    int adjcount = out_size - YSZ;
    if (adjcount > 0) {
        if (adjcount > 3 * VV * VV) adjcount = 3 * VV * VV;
        k_copyadj<<<8, 256>>>(adj, out, adjcount);
    }
}

// round 2
// speedup vs baseline: 1.0575x; 1.0575x over previous
#include <cuda_runtime.h>

typedef unsigned long long ull;

#define NB   64
#define CC   64
#define TT   300
#define VV   25
#define TV   7500
#define ICn  16
#define OCn  64
#define KS   3
#define KT   9
#define YSZ  30720000
#define BN_CNT 480000.0f

// ---------------- f32x2 helpers (FFMA2) ----------------
__device__ __forceinline__ ull fma2(ull a, ull b, ull c) {
    ull d;
    asm("fma.rn.f32x2 %0,%1,%2,%3;" : "=l"(d) : "l"(a), "l"(b), "l"(c));
    return d;
}
__device__ __forceinline__ ull dup2(float v) {
    ull d; asm("mov.b64 %0,{%1,%1};" : "=l"(d) : "f"(v)); return d;
}
__device__ __forceinline__ float2 unpk(ull a) {
    float2 r; asm("mov.b64 {%0,%1},%2;" : "=f"(r.x), "=f"(r.y) : "l"(a)); return r;
}

// ---------------- scratch ----------------
__device__ float g_fa[KS*NB*ICn*TV];
__device__ float g_fb[KS*NB*ICn*TV];
__device__ float g_S [KS*NB*VV*VV];
__device__ float g_y1[(size_t)NB*OCn*TV];
__device__ float g_ps[NB*OCn];
__device__ float g_pq[NB*OCn];
__device__ float g_stats[4*OCn];

// ---------------- K1: fa/fb 1x1 projections (f32x2, row-pair packed) --------
__global__ void __launch_bounds__(256) k_projab(const float* __restrict__ x,
        const float* __restrict__ Wa, const float* __restrict__ ba,
        const float* __restrict__ Wb, const float* __restrict__ bb) {
    __shared__ __align__(16) float ws2[64*96];   // [c][row] so row-pairs are contiguous
    int tid = threadIdx.x;
    for (int i = tid; i < 48*64; i += 256) {
        int r = i >> 6, c = i & 63;
        ws2[c*96 + r]      = Wa[i];
        ws2[c*96 + 48 + r] = Wb[i];
    }
    __syncthreads();
    int n = blockIdx.y;
    int base = blockIdx.x * 1024 + tid;
    const float* xn = x + n * CC * TV;

    for (int p = 0; p < 6; p++) {
        ull acc2[8][4];
        #pragma unroll
        for (int jj = 0; jj < 8; jj++)
            #pragma unroll
            for (int m = 0; m < 4; m++) acc2[jj][m] = 0ull;
        #pragma unroll 2
        for (int c = 0; c < 64; c++) {
            ull xd[4];
            #pragma unroll
            for (int m = 0; m < 4; m++) {
                int tv = base + m * 256;
                xd[m] = dup2((tv < TV) ? xn[c * TV + tv] : 0.f);
            }
            const ull* wp = (const ull*)(ws2 + c*96 + p*16);
            #pragma unroll
            for (int jj = 0; jj < 8; jj++) {
                ull w2 = wp[jj];
                #pragma unroll
                for (int m = 0; m < 4; m++) acc2[jj][m] = fma2(w2, xd[m], acc2[jj][m]);
            }
        }
        #pragma unroll
        for (int jj = 0; jj < 8; jj++) {
            #pragma unroll
            for (int h = 0; h < 2; h++) {
                int r = p*16 + 2*jj + h;
                float bias; float* out;
                if (r < 48) {
                    bias = ba[r];
                    out = g_fa + ((r >> 4) * NB * ICn + n * ICn + (r & 15)) * TV;
                } else {
                    int r2 = r - 48;
                    bias = bb[r2];
                    out = g_fb + ((r2 >> 4) * NB * ICn + n * ICn + (r2 & 15)) * TV;
                }
                #pragma unroll
                for (int m = 0; m < 4; m++) {
                    int tv = base + m * 256;
                    if (tv < TV) {
                        float2 f = unpk(acc2[jj][m]);
                        out[tv] = (h ? f.y : f.x) + bias;
                    }
                }
            }
        }
    }
}

// ---------------- K2: attention scores + softmax + A ----------------
__global__ void k_scoreS(const float* __restrict__ adj, const float* __restrict__ PA) {
    int kk = blockIdx.x / NB, n = blockIdx.x % NB;
    const float* fa = g_fa + (kk * NB * ICn + n * ICn) * TV;
    const float* fb = g_fb + (kk * NB * ICn + n * ICn) * TV;
    __shared__ float as[64*25], bs[64*25], Ssm[625];
    int tid = threadIdx.x;                 // 640 threads
    int v = tid / 25, w = tid - v * 25;
    bool act = tid < 625;
    float acc = 0.f;
    for (int d0 = 0; d0 < 4800; d0 += 64) {
        for (int i = tid; i < 1600; i += 640) {
            as[i] = fa[d0 * 25 + i];
            bs[i] = fb[d0 * 25 + i];
        }
        __syncthreads();
        if (act) {
            #pragma unroll 8
            for (int d = 0; d < 64; d++) acc = fmaf(as[d*25 + v], bs[d*25 + w], acc);
        }
        __syncthreads();
    }
    if (act) Ssm[tid] = acc * (1.f / 4800.f);
    __syncthreads();
    if (tid < 25) {
        int wq = tid;
        float m = -1e30f;
        #pragma unroll
        for (int vi = 0; vi < 25; vi++) m = fmaxf(m, Ssm[vi*25 + wq]);
        float e[25]; float s = 0.f;
        #pragma unroll
        for (int vi = 0; vi < 25; vi++) { e[vi] = expf(Ssm[vi*25 + wq] - m); s += e[vi]; }
        float inv = 1.f / s;
        #pragma unroll
        for (int vi = 0; vi < 25; vi++) {
            int ai = (kk * VV + vi) * VV + wq;
            g_S[(kk * NB + n) * 625 + vi * 25 + wq] = e[vi] * inv + adj[ai] + PA[ai];
        }
    }
}

// ---------------- K3: fused GCN (x·S mix + Wd projection), no g_u -----------
// Per block: n fixed, 4 t values (100 tw). Computes y1_pre[n, :, tchunk].
#define GC_S   0                   // S padded [3][25][26] = 2028
#define GC_W   2028                // Wd [kc][o]           = 12288
#define GC_X   14316               // x  [c][100]          = 6400
#define GC_Z   20716               // Z  [kc][100] + pad   = 19328
#define GC_TOT 40044               // floats (160176 bytes)
__global__ void __launch_bounds__(256) k_gcn(const float* __restrict__ x,
        const float* __restrict__ Wd, const float* __restrict__ bd) {
    extern __shared__ float sm[];
    float* S_s  = sm + GC_S;
    float* Wd_s = sm + GC_W;
    float* x_s  = sm + GC_X;
    float* Z_s  = sm + GC_Z;
    int tid = threadIdx.x;
    int n = blockIdx.y;
    int tile0 = blockIdx.x * 100;

    for (int i = tid; i < 1875; i += 256) {
        int k = i / 625, r = i - k * 625;
        int v = r / 25, w = r - v * 25;
        S_s[k*650 + v*26 + w] = g_S[(k * NB + n) * 625 + r];
    }
    for (int i = tid; i < 75; i += 256) {
        int k = i / 25, v = i - k * 25;
        S_s[k*650 + v*26 + 25] = 0.f;
    }
    for (int i = tid; i < 12288; i += 256) {
        int kc = i >> 6, o = i & 63;
        int k = kc >> 6, c = kc & 63;
        Wd_s[i] = Wd[(k*64 + o)*64 + c];
    }
    for (int i = tid; i < 6400; i += 256) {
        int c = i / 100, j = i - c * 100;
        x_s[i] = x[(n * CC + c) * TV + tile0 + j];    // 75*100==TV, always valid
    }
    __syncthreads();

    // ---- mixing: Z[kc, t*25+w] = sum_v x[c, t*25+v] * S[k, v, w] ----
    for (int r = 0; r < 3; r++) {
        int task = r * 256 + tid;          // 768 tasks = 192 kc x 4 t
        int kc = task >> 2, t = task & 3;
        int k = kc >> 6, c = kc & 63;
        ull acc2[13];
        #pragma unroll
        for (int p = 0; p < 13; p++) acc2[p] = 0ull;
        const float* xrow = x_s + c * 100 + t * 25;
        const float* Srow = S_s + k * 650;
        #pragma unroll 5
        for (int v = 0; v < 25; v++) {
            ull xd = dup2(xrow[v]);
            const ull* sp = (const ull*)(Srow + v * 26);
            #pragma unroll
            for (int p = 0; p < 13; p++) acc2[p] = fma2(sp[p], xd, acc2[p]);
        }
        float* zr = Z_s + kc * 100 + t * 25;
        #pragma unroll
        for (int p = 0; p < 12; p++) {
            float2 f = unpk(acc2[p]);
            zr[2*p] = f.x; zr[2*p+1] = f.y;
        }
        zr[24] = unpk(acc2[12]).x;
    }
    __syncthreads();

    // ---- projection: y[o, j] = sum_kc Wd[kc,o] * Z[kc,j] ----
    int ty = tid >> 5, tx = tid & 31;
    int ob = ty * 8;
    ull acc2[4][4];
    #pragma unroll
    for (int a = 0; a < 4; a++)
        #pragma unroll
        for (int m = 0; m < 4; m++) acc2[a][m] = 0ull;
    #pragma unroll 4
    for (int kc = 0; kc < 192; kc++) {
        ull zd[4];
        #pragma unroll
        for (int m = 0; m < 4; m++) zd[m] = dup2(Z_s[kc*100 + tx + 32*m]);
        const ull* wp = (const ull*)(Wd_s + kc*64 + ob);
        #pragma unroll
        for (int a = 0; a < 4; a++) {
            ull w2 = wp[a];
            #pragma unroll
            for (int m = 0; m < 4; m++) acc2[a][m] = fma2(w2, zd[m], acc2[a][m]);
        }
    }
    #pragma unroll
    for (int a = 0; a < 4; a++) {
        int o0 = ob + 2*a;
        float b0 = bd[o0]   + bd[64+o0]   + bd[128+o0];
        float b1 = bd[o0+1] + bd[64+o0+1] + bd[128+o0+1];
        #pragma unroll
        for (int m = 0; m < 4; m++) {
            int j = tx + 32*m;
            if (j < 100) {
                float2 f = unpk(acc2[a][m]);
                g_y1[(size_t)(n*OCn + o0  ) * TV + tile0 + j] = f.x + b0;
                g_y1[(size_t)(n*OCn + o0+1) * TV + tile0 + j] = f.y + b1;
            }
        }
    }
}

// ---------------- BN stats (deterministic 2-stage) ----------------
__device__ __forceinline__ void bn_part_body(const float* p) {
    float s = 0.f, q = 0.f;
    for (int i = threadIdx.x; i < TV; i += 256) { float v = p[i]; s += v; q = fmaf(v, v, q); }
    __shared__ float sh[512];
    sh[threadIdx.x] = s; sh[256 + threadIdx.x] = q;
    __syncthreads();
    for (int st = 128; st; st >>= 1) {
        if (threadIdx.x < st) {
            sh[threadIdx.x] += sh[threadIdx.x + st];
            sh[256 + threadIdx.x] += sh[256 + threadIdx.x + st];
        }
        __syncthreads();
    }
    if (threadIdx.x == 0) {
        int n = blockIdx.x, o = blockIdx.y;
        g_ps[o * 64 + n] = sh[0];
        g_pq[o * 64 + n] = sh[256];
    }
}
__global__ void k_part_y1() { bn_part_body(g_y1 + (size_t)(blockIdx.x * 64 + blockIdx.y) * TV); }
__global__ void k_part_src(const float* __restrict__ s) { bn_part_body(s + (size_t)(blockIdx.x * 64 + blockIdx.y) * TV); }

__global__ void k_bnfinal(int off) {
    int o = threadIdx.x;
    if (o < 64) {
        float s = 0.f, q = 0.f;
        for (int n = 0; n < 64; n++) { s += g_ps[o * 64 + n]; q += g_pq[o * 64 + n]; }
        g_stats[off + o] = s;
        g_stats[off + 64 + o] = q;
    }
}

// ---------------- K6: temporal conv, f32x2, BN1+residual+relu fused on load -
__global__ void __launch_bounds__(256) k_tcn(const float* __restrict__ Wt,
                                             const float* __restrict__ bt,
                                             const float* __restrict__ x,
                                             const float* __restrict__ g1,
                                             const float* __restrict__ b1,
                                             float* __restrict__ out) {
    __shared__ float ys[8 * 456];
    __shared__ __align__(16) float wsm[8 * 9 * 64];
    __shared__ float csc[64], csh[64];
    int n = blockIdx.y;
    int tile0 = blockIdx.x * 256;
    int tid = threadIdx.x;
    int ty = tid >> 5, tx = tid & 31;
    int ob = ty * 8;
    if (tid < 64) {
        const float inv = 1.f / BN_CNT;
        float mu  = g_stats[tid] * inv;
        float var = fmaf(-mu, mu, g_stats[64 + tid] * inv);
        float sc  = rsqrtf(var + 1e-5f) * g1[tid];
        csc[tid] = sc;
        csh[tid] = fmaf(-mu, sc, b1[tid]);
    }
    ull acc2[4][8];
    #pragma unroll
    for (int a = 0; a < 4; a++)
        #pragma unroll
        for (int j = 0; j < 8; j++) acc2[a][j] = 0ull;
    __syncthreads();

    for (int c0 = 0; c0 < 64; c0 += 8) {
        __syncthreads();
        for (int i = tid; i < 8 * 456; i += 256) {
            int c = i / 456, off = i - c * 456;
            int tw = tile0 - 100 + off;
            int cc = c0 + c;
            float v = 0.f;
            if (tw >= 0 && tw < TV) {
                int gi = (n * CC + cc) * TV + tw;
                float raw = g_y1[gi];
                v = fmaf(raw, csc[cc], csh[cc]) + x[gi];
                v = fmaxf(v, 0.f);
            }
            ys[i] = v;
        }
        for (int i = tid; i < 8 * 9 * 64; i += 256) {
            int o = i & 63, ck = i >> 6;
            int c = ck / 9, kt = ck - c * 9;
            wsm[i] = Wt[(o * 64 + c0 + c) * 9 + kt];
        }
        __syncthreads();
        for (int c = 0; c < 8; c++) {
            #pragma unroll 3
            for (int kt = 0; kt < 9; kt++) {
                int ybase = c * 456 + 100 + 25 * (kt - 4) + tx;
                ull yd[8];
                #pragma unroll
                for (int j = 0; j < 8; j++) yd[j] = dup2(ys[ybase + 32 * j]);
                const ull* wp = (const ull*)(wsm + (c * 9 + kt) * 64 + ob);
                #pragma unroll
                for (int a = 0; a < 4; a++) {
                    ull w2 = wp[a];
                    #pragma unroll
                    for (int j = 0; j < 8; j++)
                        acc2[a][j] = fma2(w2, yd[j], acc2[a][j]);
                }
            }
        }
    }
    #pragma unroll
    for (int a = 0; a < 4; a++) {
        int o0 = ob + 2*a;
        float b0 = bt[o0], b1v = bt[o0+1];
        #pragma unroll
        for (int j = 0; j < 8; j++) {
            int tw = tile0 + tx + 32 * j;
            if (tw < TV) {
                float2 f = unpk(acc2[a][j]);
                out[(size_t)(n * OCn + o0  ) * TV + tw] = f.x + b0;
                out[(size_t)(n * OCn + o0+1) * TV + tw] = f.y + b1v;
            }
        }
    }
}

// ---------------- BN2 apply + residual + relu ----------------
__global__ void k_bn2(float* __restrict__ out, const float* __restrict__ x,
                      const float* __restrict__ g2, const float* __restrict__ b2) {
    int idx = blockIdx.x * 256 + threadIdx.x;
    if (idx >= YSZ) return;
    int c = (idx / TV) & 63;
    const float inv = 1.f / BN_CNT;
    float mu  = g_stats[128 + c] * inv;
    float var = fmaf(-mu, mu, g_stats[192 + c] * inv);
    float sc  = rsqrtf(var + 1e-5f) * g2[c];
    float v   = (out[idx] - mu) * sc + b2[c] + x[idx];
    out[idx] = fmaxf(v, 0.f);
}

// ---------------- adj passthrough ----------------
__global__ void k_copyadj(const float* __restrict__ adj, float* __restrict__ out, int count) {
    int i = blockIdx.x * 256 + threadIdx.x;
    if (i < count) out[YSZ + i] = adj[i];
}

// ---------------- launch ----------------
extern "C" void kernel_launch(void* const* d_in, const int* in_sizes, int n_in,
                              void* d_out, int out_size) {
    const float* x   = (const float*)d_in[0];
    const float* adj = (const float*)d_in[1];
    const float* PA  = (const float*)d_in[2];
    const float* Wa  = (const float*)d_in[3];
    const float* ba  = (const float*)d_in[4];
    const float* Wb  = (const float*)d_in[5];
    const float* bb  = (const float*)d_in[6];
    const float* Wd  = (const float*)d_in[7];
    const float* bd  = (const float*)d_in[8];
    const float* g1  = (const float*)d_in[9];
    const float* b1  = (const float*)d_in[10];
    const float* Wt  = (const float*)d_in[11];
    const float* bt  = (const float*)d_in[12];
    const float* g2  = (const float*)d_in[13];
    const float* b2  = (const float*)d_in[14];
    float* out = (float*)d_out;

    static int smem_set = 0;
    if (!smem_set) {
        cudaFuncSetAttribute(k_gcn, cudaFuncAttributeMaxDynamicSharedMemorySize,
                             GC_TOT * sizeof(float));
        smem_set = 1;
    }

    k_projab<<<dim3(8, 64), 256>>>(x, Wa, ba, Wb, bb);
    k_scoreS<<<192, 640>>>(adj, PA);
    k_gcn<<<dim3(75, 64), 256, GC_TOT * sizeof(float)>>>(x, Wd, bd);

    k_part_y1<<<dim3(64, 64), 256>>>();
    k_bnfinal<<<1, 64>>>(0);

    k_tcn<<<dim3(30, 64), 256>>>(Wt, bt, x, g1, b1, out);

    k_part_src<<<dim3(64, 64), 256>>>(out);
    k_bnfinal<<<1, 64>>>(128);
    k_bn2<<<(YSZ + 255) / 256, 256>>>(out, x, g2, b2);

    int adjcount = out_size - YSZ;
    if (adjcount > 0) {
        if (adjcount > 3 * VV * VV) adjcount = 3 * VV * VV;
        k_copyadj<<<8, 256>>>(adj, out, adjcount);
    }
}